// round 7
// baseline (speedup 1.0000x reference)
#include <cuda_runtime.h>
#include <cstdint>

// Problem constants
#define B   128
#define T   1024
#define H   512
#define G   2048   // 4*H gate columns
#define V   256
#define NBLK 128   // 32 h-unit groups x 4 batch groups
#define NTHR 256   // 8 warps: 2 b-halves x 4 g-quarters, octet-k interleave inside warp
#define BT   32    // batch tile per block
#define GC   64    // gate cols per block (16 h-units x 4 gates)

// Padded smem strides (float2 units per k2 row) -> bank step 4 per k2: conflict-free
#define WST 66     // Ws2: [256][66] float2  (64 used)
#define HST 34     // Hs2: [256][34] float2  (32 used)
#define GST 68     // gates staging stride (floats)

#define WS_BYTES (256*WST*8)   // 135168
#define HS_BYTES (256*HST*8)   //  69632
#define GS_BYTES (32*GST*4)    //   8704
#define SMEM_BYTES (WS_BYTES + HS_BYTES + GS_BYTES + 256)  // 213760

// Device-global scratch (allocation-free per harness rules)
__device__ float     g_WihT[V*G];              // W_ih^T with biases folded: [v][g]
__device__ float2    g_hbuf[2][(H/2)*B];       // double-buffered h, k-pair interleaved: [k2][b]
__device__ unsigned  g_bar;

__device__ __forceinline__ void fma2(unsigned long long &d, unsigned long long a, unsigned long long b) {
    asm volatile("fma.rn.f32x2 %0, %1, %2, %0;" : "+l"(d) : "l"(a), "l"(b));
}
__device__ __forceinline__ float2 u2f(unsigned long long v) {
    float2 r; asm("mov.b64 {%0, %1}, %2;" : "=f"(r.x), "=f"(r.y) : "l"(v)); return r;
}
__device__ __forceinline__ float sigf(float x) { return 1.0f / (1.0f + expf(-x)); }

// Per-launch init: reset barrier, zero h0, build projection table
// projT[v][g] = W_ih[g][v] + b_ih[g] + b_hh[g]
__global__ void init_kernel(const float* __restrict__ W_ih,
                            const float* __restrict__ b_ih,
                            const float* __restrict__ b_hh) {
    int idx = blockIdx.x * blockDim.x + threadIdx.x;
    int stride = gridDim.x * blockDim.x;
    if (idx == 0) g_bar = 0u;
    for (int i = idx; i < V*G; i += stride) {
        int v = i >> 11;
        int g = i & (G - 1);
        g_WihT[i] = W_ih[g*V + v] + b_ih[g] + b_hh[g];
    }
    for (int i = idx; i < (H/2)*B; i += stride) g_hbuf[0][i] = make_float2(0.f, 0.f);
}

extern __shared__ char smem_raw[];

__global__ __launch_bounds__(NTHR, 1)
void lstm_persistent(const int* __restrict__ x, const int* __restrict__ x_len,
                     const float* __restrict__ W_hh, float* __restrict__ out) {
    float2* Ws2 = (float2*)smem_raw;                       // [256][WST] k-pair packed W slice
    float2* Hs2 = (float2*)(smem_raw + WS_BYTES);          // [256][HST] k-pair packed h tile
    float*  Gs  = (float*)(smem_raw + WS_BYTES + HS_BYTES);// [32][GST] gates
    int*   vbuf = (int*)(Gs + 32*GST);                     // [32] token ids this step
    int*   xls  = vbuf + 32;                               // [32] x_len cache

    const int tid  = threadIdx.x;
    const int hug  = blockIdx.x & 31;   // h-unit group
    const int bg   = blockIdx.x >> 5;   // batch group
    const int hu0  = hug * 16;
    const int b0   = bg * BT;

    // Warp grid: warp = (wb2 b-half, wg4 g-quarter); inside warp:
    //   octet = (bq, gq) 8b x 8g subtile, lanes within octet = k2 phase (ksub)
    const int warp = tid >> 5;
    const int lane = tid & 31;
    const int wb2 = warp & 1;
    const int wg4 = warp >> 1;
    const int oct  = lane >> 3;
    const int ksub = lane & 7;
    const int bq = oct & 1;
    const int gq = oct >> 1;
    const int bB = wb2*16 + bq*8;       // 8 batch rows
    const int gB = wg4*16 + gq*8;       // 8 gate cols (local)

    // ---- Prologue: load W_hh slice (resident all 1024 steps), x_len cache ----
    for (int i = tid; i < GC*256; i += NTHR) {
        int k2 = i >> 6, c = i & 63;
        int grow = ((c >> 4) << 9) + hu0 + (c & 15);   // gate_type*512 + hu0 + u
        Ws2[k2*WST + c] = *(const float2*)&W_hh[grow*H + 2*k2];
    }
    if (tid < BT) xls[tid] = x_len[b0 + tid];

    // Pointwise mapping (all 256 threads; c lives in registers)
    const int u2 = tid >> 5;   // 0..7 (h-unit pair index)
    const int pb = tid & 31;   // batch row
    float2 creg = make_float2(0.f, 0.f);

    // Projection gather row base for this lane's store row (bi == ksub):
    // global gate row for local col gB+j = wg4*512 + hu0 + gq*8 + j
    const int prow = wg4*512 + hu0 + gq*8;

    for (int t = 0; t < T; ++t) {
        // ---- Fill Hs2 from global h (double-buffered), stride HST ----
        {
            const float4* src = (const float4*)(g_hbuf[t & 1]);
            float4* dst = (float4*)Hs2;   // 17 float4 per k2 row
            #pragma unroll
            for (int i = tid; i < 4096; i += NTHR) {
                int k2 = i >> 4, q = i & 15;
                dst[k2*17 + q] = src[k2*64 + (b0 >> 1) + q];
            }
        }
        if (tid < BT) vbuf[tid] = x[(b0 + tid)*T + t];
        __syncthreads();

        // ---- Prefetch projection for this lane's output row (hidden under GEMM) ----
        int vb = vbuf[bB + ksub];
        const float* pr = &g_WihT[vb*G + prow];
        float4 proj0 = *(const float4*)pr;
        float4 proj1 = *(const float4*)(pr + 4);

        // ---- GEMM: 8b x 8g per lane, lane-private k2 = 8j + ksub ----
        unsigned long long acc[8][8];
        #pragma unroll
        for (int b = 0; b < 8; ++b)
            #pragma unroll
            for (int g = 0; g < 8; ++g) acc[b][g] = 0ull;

        const char* hp = (const char*)(Hs2 + ksub*HST + bB);
        const char* wp = (const char*)(Ws2 + ksub*WST + gB);
        #pragma unroll 2
        for (int j = 0; j < 32; ++j) {
            ulonglong2 hv0 = *(const ulonglong2*)hp;
            ulonglong2 hv1 = *(const ulonglong2*)(hp + 16);
            ulonglong2 hv2 = *(const ulonglong2*)(hp + 32);
            ulonglong2 hv3 = *(const ulonglong2*)(hp + 48);
            ulonglong2 wv0 = *(const ulonglong2*)wp;
            ulonglong2 wv1 = *(const ulonglong2*)(wp + 16);
            ulonglong2 wv2 = *(const ulonglong2*)(wp + 32);
            ulonglong2 wv3 = *(const ulonglong2*)(wp + 48);
            unsigned long long h8[8] = {hv0.x, hv0.y, hv1.x, hv1.y, hv2.x, hv2.y, hv3.x, hv3.y};
            unsigned long long w8[8] = {wv0.x, wv0.y, wv1.x, wv1.y, wv2.x, wv2.y, wv3.x, wv3.y};
            #pragma unroll
            for (int b = 0; b < 8; ++b)
                #pragma unroll
                for (int g = 0; g < 8; ++g)
                    fma2(acc[b][g], h8[b], w8[g]);
            hp += 8*HST*8;
            wp += 8*WST*8;
        }

        // ---- k-pair + octet-butterfly reduction, add proj, stage to Gs ----
        #pragma unroll
        for (int bi = 0; bi < 8; ++bi) {
            float s[8];
            #pragma unroll
            for (int gi = 0; gi < 8; ++gi) {
                float2 a = u2f(acc[bi][gi]);
                float v = a.x + a.y;
                v += __shfl_xor_sync(0xffffffffu, v, 1);
                v += __shfl_xor_sync(0xffffffffu, v, 2);
                v += __shfl_xor_sync(0xffffffffu, v, 4);
                s[gi] = v;
            }
            if (ksub == bi) {
                float4 v0 = make_float4(s[0] + proj0.x, s[1] + proj0.y,
                                        s[2] + proj0.z, s[3] + proj0.w);
                float4 v1 = make_float4(s[4] + proj1.x, s[5] + proj1.y,
                                        s[6] + proj1.z, s[7] + proj1.w);
                float* row = &Gs[(bB + bi)*GST + gB];
                *(float4*)row = v0;
                *(float4*)(row + 4) = v1;
            }
        }
        __syncthreads();

        // ---- Pointwise LSTM cell (2 h-units per thread, c in registers) ----
        {
            int b = pb;
            int base = b*GST + 2*u2;
            float2 iv = *(float2*)&Gs[base];
            float2 fv = *(float2*)&Gs[base + 16];
            float2 gv = *(float2*)&Gs[base + 32];
            float2 ov = *(float2*)&Gs[base + 48];
            float2 hprev = Hs2[((hu0 >> 1) + u2)*HST + b];

            float ia = sigf(iv.x), ib = sigf(iv.y);
            float fa = sigf(fv.x), fb = sigf(fv.y);
            float ga = tanhf(gv.x), gb = tanhf(gv.y);
            float oa = sigf(ov.x), ob = sigf(ov.y);
            float ca = fa*creg.x + ia*ga;
            float cb = fb*creg.y + ib*gb;
            float ha = oa*tanhf(ca);
            float hb = ob*tanhf(cb);

            bool m = (t < xls[b]);
            float hca = m ? ha : hprev.x;
            float hcb = m ? hb : hprev.y;
            if (m) { creg.x = ca; creg.y = cb; }

            // carried h -> next-step buffer (coalesced 256B per warp)
            g_hbuf[(t + 1) & 1][((hu0 >> 1) + u2)*B + b0 + b] = make_float2(hca, hcb);

            // sequence output
            float2 outv = m ? make_float2(ha, hb) : make_float2(0.f, 0.f);
            size_t obase = ((size_t)(b0 + b)*T + t)*H + hu0 + 2*u2;
            *(float2*)&out[obase] = outv;

            if (t == T - 1) {
                size_t hoff = (size_t)B*T*H + (size_t)(b0 + b)*H + hu0 + 2*u2;
                *(float2*)&out[hoff] = make_float2(hca, hcb);
                *(float2*)&out[hoff + (size_t)B*H] = creg;
            }
        }

        // ---- Grid barrier (all 128 blocks co-resident by construction) ----
        if (t + 1 < T) {
            __syncthreads();
            if (tid == 0) {
                __threadfence();
                atomicAdd(&g_bar, 1u);
                unsigned target = (unsigned)NBLK * (unsigned)(t + 1);
                while (*((volatile unsigned*)&g_bar) < target) { }
                __threadfence();
            }
            __syncthreads();
        }
    }
}

extern "C" void kernel_launch(void* const* d_in, const int* in_sizes, int n_in,
                              void* d_out, int out_size) {
    const int*   x     = (const int*)d_in[0];
    const int*   x_len = (const int*)d_in[1];
    const float* W_ih  = (const float*)d_in[2];
    const float* W_hh  = (const float*)d_in[3];
    const float* b_ih  = (const float*)d_in[4];
    const float* b_hh  = (const float*)d_in[5];
    float* out = (float*)d_out;

    cudaFuncSetAttribute(lstm_persistent,
                         cudaFuncAttributeMaxDynamicSharedMemorySize, SMEM_BYTES);

    init_kernel<<<256, 256>>>(W_ih, b_ih, b_hh);
    lstm_persistent<<<NBLK, NTHR, SMEM_BYTES>>>(x, x_len, W_hh, out);
}

// round 11
// speedup vs baseline: 1.3055x; 1.3055x over previous
#include <cuda_runtime.h>
#include <cuda_fp16.h>
#include <cstdint>

// Problem constants
#define B_   128
#define T_   1024
#define H_   512
#define G_   2048
#define V_   256
#define NBLK 128      // 32 gate-groups (16 units) x 4 batch-groups (32 rows)
#define NTHR 256

// SMEM map (bytes)
//  WF: A-fragments of W slice, [pass(2)][mtile(4)][kstep(32)] x 512B = 131072
//  HF: B-fragments of h tile,  [pass(2)][ntile(4)][kstep(32)] x 256B =  65536
//  GS: 4 k-split partial gate buffers [64 g][33 b] f32              =  33792
#define SM_WF  0
#define SM_HF  131072
#define SM_GS  196608
#define SM_XLS 230400
#define SMEM_BYTES 230528

// Device-global scratch (allocation-free per harness rules)
__device__ float    g_WihT[V_*G_];        // projT[v][g] with biases folded
__device__ float    g_h[2][B_*H_];        // double-buffered h, [b][k] fp32
__device__ unsigned g_bar;

__device__ __forceinline__ float sigf(float x) { return 1.0f / (1.0f + expf(-x)); }

__device__ __forceinline__ void mma16816(float d[4], const uint4& a, const uint2& b) {
    asm volatile(
        "mma.sync.aligned.m16n8k16.row.col.f32.f16.f16.f32 "
        "{%0,%1,%2,%3}, {%4,%5,%6,%7}, {%8,%9}, {%0,%1,%2,%3};"
        : "+f"(d[0]), "+f"(d[1]), "+f"(d[2]), "+f"(d[3])
        : "r"(a.x), "r"(a.y), "r"(a.z), "r"(a.w), "r"(b.x), "r"(b.y));
}

__device__ __forceinline__ uint32_t h2u(__half2 h) { return *(uint32_t*)&h; }

// fp32 pair -> (hi fp16x2, lo fp16x2) with lo = x - float(hi)
__device__ __forceinline__ void split2(float2 v, uint32_t& hi, uint32_t& lo) {
    __half2 h = __floats2half2_rn(v.x, v.y);
    float2 f = __half22float2(h);
    __half2 l = __floats2half2_rn(v.x - f.x, v.y - f.y);
    hi = h2u(h); lo = h2u(l);
}

// Per-launch init: reset barrier, zero h0, build projection table
// projT[v][g] = W_ih[g][v] + b_ih[g] + b_hh[g]
__global__ void init_kernel(const float* __restrict__ W_ih,
                            const float* __restrict__ b_ih,
                            const float* __restrict__ b_hh) {
    int idx = blockIdx.x * blockDim.x + threadIdx.x;
    int stride = gridDim.x * blockDim.x;
    if (idx == 0) g_bar = 0u;
    for (int i = idx; i < V_*G_; i += stride) {
        int v = i >> 11;
        int g = i & (G_ - 1);
        g_WihT[i] = W_ih[g*V_ + v] + b_ih[g] + b_hh[g];
    }
    for (int i = idx; i < B_*H_; i += stride) g_h[0][i] = 0.f;
}

extern __shared__ char smem_raw[];

__global__ __launch_bounds__(NTHR, 1)
void lstm_persistent(const int* __restrict__ x, const int* __restrict__ x_len,
                     const float* __restrict__ W_hh, float* __restrict__ out) {
    char*  sm  = smem_raw;
    float* Gs  = (float*)(sm + SM_GS);
    int*   xls = (int*)(sm + SM_XLS);

    const int tid  = threadIdx.x;
    const int lane = tid & 31;
    const int warp = tid >> 5;
    const int gg   = blockIdx.x & 31;   // gate group (16 h-units, 64 gate rows)
    const int bg   = blockIdx.x >> 5;   // batch group (32 rows)
    const int hu0  = gg * 16;
    const int b0   = bg * 32;

    // ---- Prologue: pack W slice into A-fragment layout (hi/lo fp16) ----
    // A m16n8k16 fragment: lane l holds a0=(r,c..c+1) a1=(r+8,c..) a2=(r,c+8..) a3=(r+8,c+8..)
    // with r=l>>2, c=2*(l&3). Block(pass,mt,s) = 512B, lane chunk = 16B.
    {
        const int combo = tid >> 1;        // (mt, s)
        const int half  = tid & 1;
        const int mt = combo >> 5;         // gate type 0..3 (16 rows each)
        const int s  = combo & 31;         // k-step
        char* wfhi = sm + SM_WF + (size_t)((0*4 + mt)*32 + s)*512;
        char* wflo = sm + SM_WF + (size_t)((1*4 + mt)*32 + s)*512;
        for (int l2 = half*16; l2 < half*16 + 16; ++l2) {
            const int r = l2 >> 2, c = 2*(l2 & 3);
            const float* w0 = W_hh + (size_t)(mt*512 + hu0 + r)*H_ + s*16 + c;
            const float* w1 = w0 + 8*H_;
            float2 w00 = *(const float2*)w0;
            float2 w02 = *(const float2*)(w0 + 8);
            float2 w10 = *(const float2*)w1;
            float2 w12 = *(const float2*)(w1 + 8);
            uint4 hi, lo;
            split2(w00, hi.x, lo.x);
            split2(w10, hi.y, lo.y);
            split2(w02, hi.z, lo.z);
            split2(w12, hi.w, lo.w);
            *(uint4*)(wfhi + l2*16) = hi;
            *(uint4*)(wflo + l2*16) = lo;
        }
    }
    if (tid < 32) xls[tid] = x_len[b0 + tid];
    __syncthreads();

    // GEMM roles: warp = (mg in {0,1}: 32-gate half, kh in 0..3: k quarter)
    const int mg = warp & 1;
    const int kh = warp >> 1;

    // Pointwise roles: b = tid&31, unit pair u0 = 2*(tid>>5)
    const int pb = tid & 31;
    const int u0 = (tid >> 5) * 2;
    float2 creg = make_float2(0.f, 0.f);

    // Convert roles: thread = (cb batch row, jb4 k-phase, ihalf k-step half)
    const int cb    = tid >> 3;           // 0..31
    const int jb4   = tid & 3;            // 0..3
    const int ihalf = (tid >> 2) & 1;     // 0..1
    const int cnt   = cb >> 3;            // B n-tile
    const int cl2   = (cb & 7)*4 + jb4;   // fragment lane

    for (int t = 0; t < T_; ++t) {
        const int cur = t & 1, nxt = cur ^ 1;

        // ---- Convert h -> fp16 hi/lo B-fragment tiles ----
        // B k16n8 fragment: lane l holds b0 = rows 2*(l&3)+{0,1}, b1 = rows +8, col l>>2.
        {
            const float* hrow = g_h[cur] + (size_t)(b0 + cb)*H_;
            char* hfhi = sm + SM_HF + (size_t)(cnt*32)*256;
            char* hflo = hfhi + 4*32*256;
            #pragma unroll 4
            for (int i = ihalf*16; i < ihalf*16 + 16; ++i) {
                float2 v0 = *(const float2*)(hrow + 2*jb4 + 16*i);      // b0 halves
                float2 v1 = *(const float2*)(hrow + 2*jb4 + 16*i + 8);  // b1 halves
                uint2 hiw, low;
                split2(v0, hiw.x, low.x);
                split2(v1, hiw.y, low.y);
                const int off = i*256 + cl2*8;
                *(uint2*)(hfhi + off) = hiw;
                *(uint2*)(hflo + off) = low;
            }
        }
        __syncthreads();

        // ---- GEMM: 3-pass fp16 split, warp tile 32g x 32b over K/4 ----
        float d[2][4][4];
        #pragma unroll
        for (int a = 0; a < 2; ++a)
            #pragma unroll
            for (int b = 0; b < 4; ++b)
                #pragma unroll
                for (int c = 0; c < 4; ++c) d[a][b][c] = 0.f;

        #pragma unroll
        for (int pass = 0; pass < 3; ++pass) {
            const int pa  = (pass == 2) ? 1 : 0;   // A: hi,hi,lo
            const int pbp = (pass == 1) ? 1 : 0;   // B: hi,lo,hi
            const char* Ab = sm + SM_WF + (size_t)(pa*4 + 2*mg)*(32*512);
            const char* Bb = sm + SM_HF + (size_t)(pbp*4)*(32*256);
            #pragma unroll 4
            for (int s8 = 0; s8 < 8; ++s8) {
                const int s = kh*8 + s8;
                uint4 A0 = *(const uint4*)(Ab + s*512 + lane*16);
                uint4 A1 = *(const uint4*)(Ab + 32*512 + s*512 + lane*16);
                uint2 Bv[4];
                #pragma unroll
                for (int nt = 0; nt < 4; ++nt)
                    Bv[nt] = *(const uint2*)(Bb + nt*(32*256) + s*256 + lane*8);
                #pragma unroll
                for (int nt = 0; nt < 4; ++nt) {
                    mma16816(d[0][nt], A0, Bv[nt]);
                    mma16816(d[1][nt], A1, Bv[nt]);
                }
            }
        }

        // ---- Stage k-split partials to Gs[kh] ----
        // D m16n8: lane holds d0=(r,c) d1=(r,c+1) d2=(r+8,c) d3=(r+8,c+1)
        {
            float* gsb = Gs + kh*2112;
            const int rr = lane >> 2, cc = 2*(lane & 3);
            #pragma unroll
            for (int mt2 = 0; mt2 < 2; ++mt2) {
                const int g0 = (2*mg + mt2)*16 + rr;
                #pragma unroll
                for (int nt = 0; nt < 4; ++nt) {
                    const int col = nt*8 + cc;
                    gsb[g0*33 + col]         = d[mt2][nt][0];
                    gsb[g0*33 + col + 1]     = d[mt2][nt][1];
                    gsb[(g0+8)*33 + col]     = d[mt2][nt][2];
                    gsb[(g0+8)*33 + col + 1] = d[mt2][nt][3];
                }
            }
        }
        __syncthreads();

        // ---- Pointwise LSTM cell (2 h-units per thread, c in registers) ----
        {
            const int b = pb;
            float gv4[4][2];
            #pragma unroll
            for (int gt = 0; gt < 4; ++gt) {
                #pragma unroll
                for (int uu = 0; uu < 2; ++uu) {
                    const int g = gt*16 + u0 + uu;
                    gv4[gt][uu] = Gs[g*33 + b] + Gs[2112 + g*33 + b]
                                + Gs[2*2112 + g*33 + b] + Gs[3*2112 + g*33 + b];
                }
            }
            const int vb = x[(size_t)(b0 + b)*T_ + t];
            const float* pj = g_WihT + (size_t)vb*G_ + hu0 + u0;
            const float2 pi = *(const float2*)(pj);
            const float2 pf = *(const float2*)(pj + 512);
            const float2 pg = *(const float2*)(pj + 1024);
            const float2 po = *(const float2*)(pj + 1536);
            const float2 hprev = *(const float2*)(g_h[cur] + (size_t)(b0+b)*H_ + hu0 + u0);

            const float ia = sigf(gv4[0][0] + pi.x), ib = sigf(gv4[0][1] + pi.y);
            const float fa = sigf(gv4[1][0] + pf.x), fb = sigf(gv4[1][1] + pf.y);
            const float ga = tanhf(gv4[2][0] + pg.x), gb = tanhf(gv4[2][1] + pg.y);
            const float oa = sigf(gv4[3][0] + po.x), ob = sigf(gv4[3][1] + po.y);
            const float ca  = fa*creg.x + ia*ga;
            const float cb2 = fb*creg.y + ib*gb;
            const float ha = oa*tanhf(ca);
            const float hb = ob*tanhf(cb2);

            const bool m = (t < xls[b]);
            const float hca = m ? ha : hprev.x;
            const float hcb = m ? hb : hprev.y;
            if (m) { creg.x = ca; creg.y = cb2; }

            *(float2*)(g_h[nxt] + (size_t)(b0+b)*H_ + hu0 + u0) = make_float2(hca, hcb);

            const float2 outv = m ? make_float2(ha, hb) : make_float2(0.f, 0.f);
            *(float2*)(out + ((size_t)(b0+b)*T_ + t)*H_ + hu0 + u0) = outv;

            if (t == T_ - 1) {
                const size_t hoff = (size_t)B_*T_*H_ + (size_t)(b0+b)*H_ + hu0 + u0;
                *(float2*)(out + hoff) = make_float2(hca, hcb);
                *(float2*)(out + hoff + (size_t)B_*H_) = creg;
            }
        }

        // ---- Grid barrier (128 CTAs, 1/SM, co-resident) ----
        if (t + 1 < T_) {
            __threadfence();          // release all this block's stores
            __syncthreads();
            if (tid == 0) {
                atomicAdd(&g_bar, 1u);
                const unsigned target = (unsigned)NBLK * (unsigned)(t + 1);
                while (*((volatile unsigned*)&g_bar) < target) { }
                __threadfence();      // acquire + L1D invalidate
            }
            __syncthreads();
        }
    }
}

extern "C" void kernel_launch(void* const* d_in, const int* in_sizes, int n_in,
                              void* d_out, int out_size) {
    const int*   x     = (const int*)d_in[0];
    const int*   x_len = (const int*)d_in[1];
    const float* W_ih  = (const float*)d_in[2];
    const float* W_hh  = (const float*)d_in[3];
    const float* b_ih  = (const float*)d_in[4];
    const float* b_hh  = (const float*)d_in[5];
    float* out = (float*)d_out;

    cudaFuncSetAttribute(lstm_persistent,
                         cudaFuncAttributeMaxDynamicSharedMemorySize, SMEM_BYTES);

    init_kernel<<<256, 256>>>(W_ih, b_ih, b_hh);
    lstm_persistent<<<NBLK, NTHR, SMEM_BYTES>>>(x, x_len, W_hh, out);
}